// round 17
// baseline (speedup 1.0000x reference)
#include <cuda_runtime.h>
#include <mma.h>
#include <cuda_fp16.h>
#include <cstdint>
#include <math.h>

// Problem constants
constexpr int Bb = 2, Ss = 2048, Ee = 4096, Hh = 16, Dd = 256, Rr = 64;
constexpr int Mtot = Bb * Ss;                  // 4096
constexpr size_t QK_ELEMS = (size_t)Bb * Hh * Ss * Dd;   // 16777216

// GEMM tiling: CTA 128x128, 8 warps (2x4), warp tile 64x32, fp16, 3-stage pipe
constexpr int BM = 128, BN = 128, BK = 64;     // BK=64 halves = 128 bytes/row
constexpr int NTHREADS = 256;
constexpr int ASTR = BK + 8;                   // 72 halves = 144 B/row
constexpr uint32_t STAGE_A_BYTES = BM * ASTR * 2;        // 18432
constexpr uint32_t STAGE_BYTES = 2 * STAGE_A_BYTES;      // 36864
constexpr int NSTAGE = 3;
constexpr int CSTR = BN + 4;                   // 132
constexpr uint32_t GEMM_SMEM = NSTAGE * STAGE_BYTES;     // 110592 (2 CTAs/SM)

// Scratch (fp16 GEMM operands)
__device__ __half g_xnorm[(size_t)Mtot * Ee];
__device__ __half g_wq[(size_t)Ee * Ee];
__device__ __half g_wk[(size_t)Ee * Ee];
__device__ __half g_qr[QK_ELEMS];
__device__ __half g_kr[QK_ELEMS];

__device__ __forceinline__ uint32_t smem_u32(const void* p) {
    uint32_t a;
    asm("{ .reg .u64 t; cvta.to.shared.u64 t, %1; cvt.u32.u64 %0, t; }" : "=r"(a) : "l"(p));
    return a;
}
__device__ __forceinline__ void cp16(uint32_t dst, const void* src) {
    asm volatile("cp.async.cg.shared.global [%0], [%1], 16;" :: "r"(dst), "l"(src));
}
__device__ __forceinline__ void stcs2(float* p, float2 v) {
    asm volatile("st.global.cs.v2.f32 [%0], {%1, %2};" :: "l"(p), "f"(v.x), "f"(v.y) : "memory");
}
__device__ __forceinline__ void stcs4(float* p, float4 v) {
    asm volatile("st.global.cs.v4.f32 [%0], {%1, %2, %3, %4};"
                 :: "l"(p), "f"(v.x), "f"(v.y), "f"(v.z), "f"(v.w) : "memory");
}
#define CP_COMMIT() asm volatile("cp.async.commit_group;" ::: "memory")
#define CP_WAIT1()  asm volatile("cp.async.wait_group 1;" ::: "memory")

// ---------------------------------------------------------------------------
// mma.sync + ldmatrix primitives
// ---------------------------------------------------------------------------
__device__ __forceinline__ void ldsm4(uint32_t addr, uint32_t* r) {
    asm volatile("ldmatrix.sync.aligned.m8n8.x4.shared.b16 {%0,%1,%2,%3}, [%4];"
                 : "=r"(r[0]), "=r"(r[1]), "=r"(r[2]), "=r"(r[3]) : "r"(addr));
}
__device__ __forceinline__ void mma16816(float* c, const uint32_t* a, const uint32_t* b) {
    asm volatile("mma.sync.aligned.m16n8k16.row.col.f32.f16.f16.f32 "
                 "{%0,%1,%2,%3}, {%4,%5,%6,%7}, {%8,%9}, {%0,%1,%2,%3};"
                 : "+f"(c[0]), "+f"(c[1]), "+f"(c[2]), "+f"(c[3])
                 : "r"(a[0]), "r"(a[1]), "r"(a[2]), "r"(a[3]), "r"(b[0]), "r"(b[1]));
}

// ---------------------------------------------------------------------------
// LayerNorm -> fp16 g_xnorm
// ---------------------------------------------------------------------------
__global__ void __launch_bounds__(256) ln_kernel(const float* __restrict__ x,
                                                 const float* __restrict__ w,
                                                 const float* __restrict__ b) {
    int row = blockIdx.x;
    int tid = threadIdx.x;
    const float4* xr = reinterpret_cast<const float4*>(x + (size_t)row * Ee);

    float4 v[4];
    float sum = 0.f, ssq = 0.f;
#pragma unroll
    for (int j = 0; j < 4; j++) {
        v[j] = xr[tid + j * 256];
        sum += v[j].x + v[j].y + v[j].z + v[j].w;
        ssq += v[j].x * v[j].x + v[j].y * v[j].y + v[j].z * v[j].z + v[j].w * v[j].w;
    }
    __shared__ float s_sum[8], s_ssq[8];
#pragma unroll
    for (int o = 16; o; o >>= 1) {
        sum += __shfl_xor_sync(~0u, sum, o);
        ssq += __shfl_xor_sync(~0u, ssq, o);
    }
    if ((tid & 31) == 0) { s_sum[tid >> 5] = sum; s_ssq[tid >> 5] = ssq; }
    __syncthreads();
    if (tid < 32) {
        float ts = (tid < 8) ? s_sum[tid] : 0.f;
        float tq = (tid < 8) ? s_ssq[tid] : 0.f;
#pragma unroll
        for (int o = 4; o; o >>= 1) {
            ts += __shfl_xor_sync(~0u, ts, o);
            tq += __shfl_xor_sync(~0u, tq, o);
        }
        if (tid == 0) { s_sum[0] = ts; s_ssq[0] = tq; }
    }
    __syncthreads();
    float mean = s_sum[0] * (1.0f / Ee);
    float var = s_ssq[0] * (1.0f / Ee) - mean * mean;
    float rstd = rsqrtf(var + 1e-5f);

    const float4* wr = reinterpret_cast<const float4*>(w);
    const float4* br = reinterpret_cast<const float4*>(b);
    __half2* outr = reinterpret_cast<__half2*>(g_xnorm + (size_t)row * Ee);
#pragma unroll
    for (int j = 0; j < 4; j++) {
        int c = tid + j * 256;
        float4 wv = wr[c], bv = br[c];
        float o0 = (v[j].x - mean) * rstd * wv.x + bv.x;
        float o1 = (v[j].y - mean) * rstd * wv.y + bv.y;
        float o2 = (v[j].z - mean) * rstd * wv.z + bv.z;
        float o3 = (v[j].w - mean) * rstd * wv.w + bv.w;
        outr[c * 2]     = __floats2half2_rn(o0, o1);
        outr[c * 2 + 1] = __floats2half2_rn(o2, o3);
    }
}

// ---------------------------------------------------------------------------
// Weight conversion fp32 -> fp16
// ---------------------------------------------------------------------------
__global__ void __launch_bounds__(256) wconv_kernel(const float* __restrict__ wq,
                                                    const float* __restrict__ wk) {
    const float* src = blockIdx.y ? wk : wq;
    __half* dst = blockIdx.y ? g_wk : g_wq;
    size_t i = ((size_t)blockIdx.x * 256 + threadIdx.x) * 4;
    float4 v = *reinterpret_cast<const float4*>(src + i);
    __half2* d2 = reinterpret_cast<__half2*>(dst + i);
    d2[0] = __floats2half2_rn(v.x, v.y);
    d2[1] = __floats2half2_rn(v.z, v.w);
}

// ---------------------------------------------------------------------------
// Pipelined fp16 GEMM (NT), CTA 128x128, warp tile 64x32, mma.sync + ldmatrix
// with cross-kk fragment double buffering. 3-stage cp.async, 2 CTAs/SM.
// ---------------------------------------------------------------------------
__device__ __forceinline__ void load_chunk(uint32_t sb, const char* Ab, const char* Bbp,
                                           size_t ldab, int kc, int buf, int tid) {
    uint32_t stA = sb + buf * STAGE_BYTES;
    uint32_t stB = stA + STAGE_A_BYTES;
    const char* Ap = Ab + (size_t)kc * (BK * 2);
    const char* Bp = Bbp + (size_t)kc * (BK * 2);
#pragma unroll
    for (int l = 0; l < 4; l++) {
        int idx = tid + l * NTHREADS;    // 0..1023
        int r = idx >> 3, cb = (idx & 7) << 4;
        cp16(stA + r * (ASTR * 2) + cb, Ap + (size_t)r * ldab + cb);
        cp16(stB + r * (ASTR * 2) + cb, Bp + (size_t)r * ldab + cb);
    }
}

template <int NCHUNK>
__device__ __forceinline__ void gemm_pipe(const char* Ab, const char* Bbp, size_t ldab,
                                          char* smem, float acc[4][4][4]) {
    uint32_t sb = smem_u32(smem);
    int tid = threadIdx.x;
    int warp = tid >> 5;
    int lane = tid & 31;
    int wm = warp & 1;        // 2 along M, 64 rows each
    int wn = warp >> 1;       // 4 along N, 32 cols each
    int t8 = lane >> 3, r8 = lane & 7;
    // ldmatrix per-lane row offsets (bytes, relative to stage bases)
    // A tiles order: m0k0, m8k0, m0k8, m8k8
    uint32_t aRow = ((uint32_t)(wm * 64 + (t8 & 1) * 8 + r8) * ASTR + (t8 >> 1) * 8) * 2;
    // B tiles order: (n0,k0), (n0,k8), (n8,k0), (n8,k8)
    uint32_t bRow = ((uint32_t)(wn * 32 + (t8 >> 1) * 8 + r8) * ASTR + (t8 & 1) * 8) * 2;

    load_chunk(sb, Ab, Bbp, ldab, 0, 0, tid);
    CP_COMMIT();
    if (NCHUNK > 1) load_chunk(sb, Ab, Bbp, ldab, 1, 1, tid);
    CP_COMMIT();

    for (int k = 0; k < NCHUNK; k++) {
        CP_WAIT1();               // chunk k resident for this thread
        __syncthreads();          // ...for all; buf (k-1)%3 fully consumed
        if (k + 2 < NCHUNK)
            load_chunk(sb, Ab, Bbp, ldab, k + 2, (k + 2) % NSTAGE, tid);
        CP_COMMIT();              // one group per iter (may be empty)

        uint32_t aBase = sb + (k % NSTAGE) * STAGE_BYTES + aRow;
        uint32_t bBase = sb + (k % NSTAGE) * STAGE_BYTES + STAGE_A_BYTES + bRow;

        uint32_t A0[4][4], A1[4][4], B0[2][4], B1[2][4];
        // prime kk=0
#pragma unroll
        for (int mt = 0; mt < 4; mt++) ldsm4(aBase + mt * (16 * ASTR * 2), A0[mt]);
#pragma unroll
        for (int g = 0; g < 2; g++)    ldsm4(bBase + g * (16 * ASTR * 2), B0[g]);

#pragma unroll
        for (int kk = 0; kk < 4; kk++) {
            uint32_t (*Ac)[4] = (kk & 1) ? A1 : A0;
            uint32_t (*Bc)[4] = (kk & 1) ? B1 : B0;
            uint32_t (*An)[4] = (kk & 1) ? A0 : A1;
            uint32_t (*Bn)[4] = (kk & 1) ? B0 : B1;
            if (kk < 3) {
                uint32_t ka = aBase + (kk + 1) * 32;   // 16 halves = 32 B
                uint32_t kb = bBase + (kk + 1) * 32;
#pragma unroll
                for (int mt = 0; mt < 4; mt++) ldsm4(ka + mt * (16 * ASTR * 2), An[mt]);
#pragma unroll
                for (int g = 0; g < 2; g++)    ldsm4(kb + g * (16 * ASTR * 2), Bn[g]);
            }
#pragma unroll
            for (int mt = 0; mt < 4; mt++)
#pragma unroll
                for (int nt = 0; nt < 4; nt++)
                    mma16816(acc[mt][nt], Ac[mt], &Bc[nt >> 1][(nt & 1) * 2]);
        }
    }
    __syncthreads();   // all reads done before smem reused for Cs
}

// Store mma.sync accumulators to smem in the same Cs layout as before.
// C frag m16n8: c0,c1 @ (row=lane>>2, col=2*(lane&3)); c2,c3 @ row+8.
__device__ __forceinline__ void store_acc(float* Cs, float acc[4][4][4]) {
    int tid = threadIdx.x;
    int warp = tid >> 5, lane = tid & 31;
    int wm = warp & 1, wn = warp >> 1;
    int r0 = lane >> 2, c0 = (lane & 3) << 1;
#pragma unroll
    for (int mt = 0; mt < 4; mt++)
#pragma unroll
        for (int nt = 0; nt < 4; nt++) {
            float* cp = Cs + (size_t)(wm * 64 + mt * 16 + r0) * CSTR + wn * 32 + nt * 8 + c0;
            *reinterpret_cast<float2*>(cp) = make_float2(acc[mt][nt][0], acc[mt][nt][1]);
            *reinterpret_cast<float2*>(cp + 8 * CSTR) = make_float2(acc[mt][nt][2], acc[mt][nt][3]);
        }
}

// ---------------------------------------------------------------------------
// Projection GEMM + bias + RoPE; fp32 q/k to d_out (streaming), fp16 copies
// ---------------------------------------------------------------------------
__global__ void __launch_bounds__(NTHREADS, 2) proj_cp_kernel(
    const float* __restrict__ bq, const float* __restrict__ bk,
    const float* __restrict__ embed, const int* __restrict__ posids,
    float* __restrict__ qout, float* __restrict__ kout)
{
    extern __shared__ __align__(128) char smem[];
    int z = blockIdx.z;
    const __half* W   = z ? g_wk : g_wq;
    const float* bias = z ? bk : bq;
    float* outp       = z ? kout : qout;
    __half* routp     = z ? g_kr : g_qr;
    const int m0 = blockIdx.x * BM;   // x fastest: consecutive CTAs share the weight panel
    const int n0 = blockIdx.y * BN;

    float acc[4][4][4];
#pragma unroll
    for (int i = 0; i < 4; i++)
#pragma unroll
        for (int j = 0; j < 4; j++)
#pragma unroll
            for (int e = 0; e < 4; e++)
                acc[i][j][e] = 0.f;

    gemm_pipe<Ee / BK>(reinterpret_cast<const char*>(g_xnorm + (size_t)m0 * Ee),
                       reinterpret_cast<const char*>(W + (size_t)n0 * Ee),
                       (size_t)Ee * 2, smem, acc);

    float* Cs = reinterpret_cast<float*>(smem);
    store_acc(Cs, acc);
    __syncthreads();

    int tid = threadIdx.x;
#pragma unroll 4
    for (int i = 0; i < 32; i++) {
        int it = tid + i * NTHREADS;     // 0..8191 over 128x64 pairs
        int r = it >> 6;                 // 0..127
        int pc = it & 63;
        int c = pc << 1;
        int m = m0 + r, f = n0 + c;
        float v0 = Cs[r * CSTR + c] + bias[f];
        float v1 = Cs[r * CSTR + c + 1] + bias[f + 1];
        int d = f & 255;
        if (d < Rr) {
            int pos = posids[m];
            int i2 = d >> 1;
            float sn = embed[pos * Rr + i2];
            float co = embed[pos * Rr + 32 + i2];
            float o0 = v0 * co - v1 * sn;
            float o1 = v1 * co + v0 * sn;
            v0 = o0; v1 = o1;
        }
        int b_ = m >> 11, s_ = m & 2047, h_ = f >> 8;
        size_t off = ((size_t)(b_ * Hh + h_) * Ss + s_) * Dd + d;
        stcs2(outp + off, make_float2(v0, v1));   // streaming: never re-read
        *reinterpret_cast<__half2*>(routp + off) = __floats2half2_rn(v0, v1);
    }
}

// ---------------------------------------------------------------------------
// Scores GEMM: scores = Qh.Kh^T / 16, causal tile skip
// ---------------------------------------------------------------------------
__global__ void __launch_bounds__(NTHREADS, 2) scores_cp_kernel(float* __restrict__ attn)
{
    int kt = blockIdx.x, qt = blockIdx.y, bh = blockIdx.z;
    if (kt > qt) return;

    extern __shared__ __align__(128) char smem[];
    int m0 = qt * BM, n0 = kt * BN;
    const __half* Q = g_qr + (size_t)bh * Ss * Dd;
    const __half* Kv = g_kr + (size_t)bh * Ss * Dd;

    float acc[4][4][4];
#pragma unroll
    for (int i = 0; i < 4; i++)
#pragma unroll
        for (int j = 0; j < 4; j++)
#pragma unroll
            for (int e = 0; e < 4; e++)
                acc[i][j][e] = 0.f;

    gemm_pipe<Dd / BK>(reinterpret_cast<const char*>(Q + (size_t)m0 * Dd),
                       reinterpret_cast<const char*>(Kv + (size_t)n0 * Dd),
                       (size_t)Dd * 2, smem, acc);

    float* Cs = reinterpret_cast<float*>(smem);
    store_acc(Cs, acc);
    __syncthreads();

    float* out_base = attn + (size_t)bh * Ss * Ss;
#pragma unroll
    for (int i = 0; i < 16; i++) {
        int it = threadIdx.x + i * NTHREADS;   // 0..4095 float4s over 128x128
        int r = it >> 5;
        int c4 = (it & 31) << 2;
        float4 v = *reinterpret_cast<const float4*>(Cs + r * CSTR + c4);
        v.x *= 0.0625f; v.y *= 0.0625f; v.z *= 0.0625f; v.w *= 0.0625f;
        stcs4(out_base + (size_t)(m0 + r) * Ss + n0 + c4, v);   // streaming
    }
}

// ---------------------------------------------------------------------------
// In-place masked softmax, float4 vectorized; final writes streaming
// ---------------------------------------------------------------------------
__global__ void __launch_bounds__(256) softmax_kernel(float* __restrict__ attn) {
    int row = blockIdx.x;
    int q = row & 2047;
    int nv = q + 1;
    float* rowp = attn + (size_t)row * Ss;
    int tid = threadIdx.x;

    float4 vals[2];
    float mx = -INFINITY;
#pragma unroll
    for (int j = 0; j < 2; j++) {
        int k4 = (tid + j * 256) << 2;
        float4 v;
        if (k4 + 3 < nv) {
            v = *reinterpret_cast<const float4*>(rowp + k4);
        } else {
            v.x = (k4 + 0 < nv) ? rowp[k4 + 0] : -INFINITY;
            v.y = (k4 + 1 < nv) ? rowp[k4 + 1] : -INFINITY;
            v.z = (k4 + 2 < nv) ? rowp[k4 + 2] : -INFINITY;
            v.w = (k4 + 3 < nv) ? rowp[k4 + 3] : -INFINITY;
        }
        vals[j] = v;
        mx = fmaxf(mx, fmaxf(fmaxf(v.x, v.y), fmaxf(v.z, v.w)));
    }
    __shared__ float sh[8];
#pragma unroll
    for (int o = 16; o; o >>= 1) mx = fmaxf(mx, __shfl_xor_sync(~0u, mx, o));
    if ((tid & 31) == 0) sh[tid >> 5] = mx;
    __syncthreads();
    if (tid < 32) {
        float t = (tid < 8) ? sh[tid] : -INFINITY;
#pragma unroll
        for (int o = 4; o; o >>= 1) t = fmaxf(t, __shfl_xor_sync(~0u, t, o));
        if (tid == 0) sh[0] = t;
    }
    __syncthreads();
    float M = sh[0];
    __syncthreads();

    float sum = 0.f;
#pragma unroll
    for (int j = 0; j < 2; j++) {
        float4 v = vals[j];
        v.x = (v.x == -INFINITY) ? 0.f : __expf(v.x - M);
        v.y = (v.y == -INFINITY) ? 0.f : __expf(v.y - M);
        v.z = (v.z == -INFINITY) ? 0.f : __expf(v.z - M);
        v.w = (v.w == -INFINITY) ? 0.f : __expf(v.w - M);
        vals[j] = v;
        sum += v.x + v.y + v.z + v.w;
    }
#pragma unroll
    for (int o = 16; o; o >>= 1) sum += __shfl_xor_sync(~0u, sum, o);
    if ((tid & 31) == 0) sh[tid >> 5] = sum;
    __syncthreads();
    if (tid < 32) {
        float t = (tid < 8) ? sh[tid] : 0.f;
#pragma unroll
        for (int o = 4; o; o >>= 1) t += __shfl_xor_sync(~0u, t, o);
        if (tid == 0) sh[0] = t;
    }
    __syncthreads();
    float inv = 1.0f / sh[0];
#pragma unroll
    for (int j = 0; j < 2; j++) {
        int k4 = (tid + j * 256) << 2;
        float4 v = vals[j];
        v.x *= inv; v.y *= inv; v.z *= inv; v.w *= inv;
        stcs4(rowp + k4, v);            // streaming: never re-read
    }
}

// ---------------------------------------------------------------------------
extern "C" void kernel_launch(void* const* d_in, const int* in_sizes, int n_in,
                              void* d_out, int out_size) {
    const float* x     = (const float*)d_in[0];
    const float* q_w   = (const float*)d_in[1];
    const float* q_b   = (const float*)d_in[2];
    const float* k_w   = (const float*)d_in[3];
    const float* k_b   = (const float*)d_in[4];
    const float* ln_w  = (const float*)d_in[5];
    const float* ln_b  = (const float*)d_in[6];
    const float* embed = (const float*)d_in[7];
    const int*   pos   = (const int*)d_in[8];

    float* out   = (float*)d_out;
    float* q_out = out;
    float* k_out = out + QK_ELEMS;
    float* attn  = out + 2 * QK_ELEMS;

    cudaFuncSetAttribute(proj_cp_kernel, cudaFuncAttributeMaxDynamicSharedMemorySize, (int)GEMM_SMEM);
    cudaFuncSetAttribute(scores_cp_kernel, cudaFuncAttributeMaxDynamicSharedMemorySize, (int)GEMM_SMEM);

    ln_kernel<<<Mtot, 256>>>(x, ln_w, ln_b);

    dim3 gw((unsigned)(((size_t)Ee * Ee) / 1024), 2);   // 16384 x 2
    wconv_kernel<<<gw, 256>>>(q_w, k_w);

    dim3 gp(Mtot / BM, Ee / BN, 2);          // (32, 32, 2), x over M
    proj_cp_kernel<<<gp, NTHREADS, GEMM_SMEM>>>(q_b, k_b, embed, pos, q_out, k_out);

    dim3 g2(Ss / BN, Ss / BM, Bb * Hh);      // (16, 16, 32)
    scores_cp_kernel<<<g2, NTHREADS, GEMM_SMEM>>>(attn);

    softmax_kernel<<<Bb * Hh * Ss, 256>>>(attn);
}